// round 5
// baseline (speedup 1.0000x reference)
#include <cuda_runtime.h>

// Shapes (fixed by the problem)
#define D_MODEL   1024
#define HEAD_DIM  64
#define NUM_HEADS 16
#define BATCH     8
#define SEQ       4096

// Scratch (allocation-free rule: __device__ globals)
__device__ float g_V[BATCH * HEAD_DIM];
__device__ float g_row[BATCH * D_MODEL];

// ---------------------------------------------------------------------------
// Kernel A: V[b,d] = bv[d] + sum_i value[b,i] * Wv[i,d]
// grid = BATCH blocks, 256 threads. Each (d, slice) pair accumulates a
// 256-long strip of i, then a small smem reduction combines 4 slices.
// ---------------------------------------------------------------------------
__global__ void compute_v_kernel(const float* __restrict__ value,
                                 const float* __restrict__ Wv,
                                 const float* __restrict__ bv) {
    const int b = blockIdx.x;
    const int t = threadIdx.x;          // 0..255
    const int d = t & (HEAD_DIM - 1);   // 0..63
    const int slice = t >> 6;           // 0..3
    const float* vrow = value + b * D_MODEL;

    float acc = 0.f;
    const int i0 = slice * (D_MODEL / 4);
    #pragma unroll 8
    for (int i = 0; i < D_MODEL / 4; ++i) {
        const int ii = i0 + i;
        acc += vrow[ii] * Wv[ii * HEAD_DIM + d];
    }

    __shared__ float red[4][HEAD_DIM];
    red[slice][d] = acc;
    __syncthreads();
    if (slice == 0) {
        float s = red[0][d] + red[1][d] + red[2][d] + red[3][d];
        g_V[b * HEAD_DIM + d] = s + bv[d];
    }
}

// ---------------------------------------------------------------------------
// Kernel B: row[b,j] = bo[j] + sum_{i<1024} V[b, i & 63] * Wo[i,j]
// grid = (4 j-chunks, 8 batches), 256 threads; each thread owns one j.
// V[b] broadcast from shared memory. Wo column reads are coalesced
// (consecutive threads -> consecutive addresses).
// ---------------------------------------------------------------------------
__global__ void compute_row_kernel(const float* __restrict__ Wo,
                                   const float* __restrict__ bo) {
    const int b = blockIdx.y;
    const int j = blockIdx.x * 256 + threadIdx.x;

    __shared__ float sV[HEAD_DIM];
    if (threadIdx.x < HEAD_DIM) sV[threadIdx.x] = g_V[b * HEAD_DIM + threadIdx.x];
    __syncthreads();

    float acc = bo[j];
    #pragma unroll 8
    for (int i = 0; i < D_MODEL; ++i) {
        acc += sV[i & (HEAD_DIM - 1)] * Wo[i * D_MODEL + j];
    }
    g_row[b * D_MODEL + j] = acc;
}

// ---------------------------------------------------------------------------
// Kernel C: out[b,s,:] = row[b,:]  (134 MB of streaming float4 stores)
// grid = (SEQ / S_PER_BLOCK, BATCH), 256 threads. Each thread holds one
// float4 of its batch's row in a register and stamps it S_PER_BLOCK times.
// ---------------------------------------------------------------------------
#define S_PER_BLOCK 32
#define ROW_VEC4    (D_MODEL / 4)   // 256

__global__ void broadcast_kernel(float4* __restrict__ out) {
    const int b = blockIdx.y;
    const int s0 = blockIdx.x * S_PER_BLOCK;
    const int t = threadIdx.x;  // 0..255 -> one float4 of the row

    const float4 v = reinterpret_cast<const float4*>(g_row)[b * ROW_VEC4 + t];

    size_t base = ((size_t)b * SEQ + s0) * ROW_VEC4 + t;
    #pragma unroll
    for (int s = 0; s < S_PER_BLOCK; ++s) {
        out[base + (size_t)s * ROW_VEC4] = v;
    }
}

// ---------------------------------------------------------------------------
// Inputs (metadata order): 0 query, 1 key, 2 value, 3 Wq, 4 bq,
//                          5 Wk, 6 bk, 7 Wv, 8 bv, 9 Wo, 10 bo
// query/key/Wq/bq/Wk/bk never touch the output (softmax over kv_len=1 is 1).
// ---------------------------------------------------------------------------
extern "C" void kernel_launch(void* const* d_in, const int* in_sizes, int n_in,
                              void* d_out, int out_size) {
    const float* value = (const float*)d_in[2];
    const float* Wv    = (const float*)d_in[7];
    const float* bv    = (const float*)d_in[8];
    const float* Wo    = (const float*)d_in[9];
    const float* bo    = (const float*)d_in[10];
    float* out = (float*)d_out;

    compute_v_kernel<<<BATCH, 256>>>(value, Wv, bv);

    dim3 gridB(D_MODEL / 256, BATCH);
    compute_row_kernel<<<gridB, 256>>>(Wo, bo);

    dim3 gridC(SEQ / S_PER_BLOCK, BATCH);
    broadcast_kernel<<<gridC, 256>>>((float4*)out);
}

// round 6
// speedup vs baseline: 2.7805x; 2.7805x over previous
#include <cuda_runtime.h>

// Shapes (fixed by the problem)
#define D_MODEL   1024
#define HEAD_DIM  64
#define NUM_HEADS 16
#define BATCH     8
#define SEQ       4096

// Scratch (allocation-free rule: __device__ globals)
__device__ float g_V[BATCH * HEAD_DIM];     // V = value @ Wv + bv
__device__ float g_row[BATCH * D_MODEL];    // row[b] = tile(V[b],16) @ Wo + bo

// ---------------------------------------------------------------------------
// Kernel A: (1) g_row[b,j] = bo[j]   (reset every call — B accumulates atomically)
//           (2) V[b,d] = bv[d] + sum_i value[b,i] * Wv[i,d]
// grid = 8 (one per batch), block = 1024 = 64 d-lanes x 16 K-slices.
// Each thread reduces a 64-long strip; smem tree combines 16 slices.
// ---------------------------------------------------------------------------
__global__ __launch_bounds__(1024, 1)
void prologue_kernel(const float* __restrict__ value,
                     const float* __restrict__ Wv,
                     const float* __restrict__ bv,
                     const float* __restrict__ bo) {
    const int b = blockIdx.x;
    const int t = threadIdx.x;          // 0..1023

    // init g_row with bias (fresh every launch; B atomically adds onto this)
    g_row[b * D_MODEL + t] = bo[t];

    const int d     = t & (HEAD_DIM - 1);   // 0..63
    const int slice = t >> 6;               // 0..15
    const int i0    = slice * (D_MODEL / 16);
    const float* vrow = value + b * D_MODEL;

    float acc = 0.f;
    #pragma unroll 16
    for (int i = 0; i < D_MODEL / 16; ++i) {
        const int ii = i0 + i;
        acc += vrow[ii] * Wv[ii * HEAD_DIM + d];
    }

    __shared__ float red[16][HEAD_DIM];
    red[slice][d] = acc;
    __syncthreads();
    if (slice == 0) {
        float s = 0.f;
        #pragma unroll
        for (int k = 0; k < 16; ++k) s += red[k][d];
        g_V[b * HEAD_DIM + d] = s + bv[d];
    }
}

// ---------------------------------------------------------------------------
// Kernel B: g_row[b,j] += sum_{ii<64} V[b,ii] * Wo[(h*64+ii)*1024 + j]
// grid = (4 j-chunks, 16 h-slices) = 64 blocks, 256 threads.
// Each Wo element is read exactly once across the grid (4 MB streaming,
// fully coalesced). All 8 batches accumulated simultaneously per thread.
// ---------------------------------------------------------------------------
__global__ __launch_bounds__(256, 1)
void row_partial_kernel(const float* __restrict__ Wo) {
    const int t = threadIdx.x;                 // 0..255
    const int j = blockIdx.x * 256 + t;        // 0..1023
    const int h = blockIdx.y;                  // 0..15

    __shared__ float sV[BATCH * HEAD_DIM];     // 512 floats
    sV[t]       = g_V[t];
    sV[t + 256] = g_V[t + 256];
    __syncthreads();

    float acc[BATCH];
    #pragma unroll
    for (int b = 0; b < BATCH; ++b) acc[b] = 0.f;

    const float* wcol = Wo + (size_t)(h * HEAD_DIM) * D_MODEL + j;
    #pragma unroll 8
    for (int ii = 0; ii < HEAD_DIM; ++ii) {
        const float w = wcol[ii * D_MODEL];    // coalesced across threads
        #pragma unroll
        for (int b = 0; b < BATCH; ++b)
            acc[b] += sV[b * HEAD_DIM + ii] * w;   // smem broadcast
    }

    #pragma unroll
    for (int b = 0; b < BATCH; ++b)
        atomicAdd(&g_row[b * D_MODEL + j], acc[b]);
}

// ---------------------------------------------------------------------------
// Kernel C: out[b,s,:] = row[b,:]  (134 MB of streaming float4 stores)
// grid = (SEQ/32, 8), 256 threads; each thread stamps its float4 32 times.
// ---------------------------------------------------------------------------
#define S_PER_BLOCK 32
#define ROW_VEC4    (D_MODEL / 4)   // 256

__global__ __launch_bounds__(256, 8)
void broadcast_kernel(float4* __restrict__ out) {
    const int b  = blockIdx.y;
    const int s0 = blockIdx.x * S_PER_BLOCK;
    const int t  = threadIdx.x;

    const float4 v = reinterpret_cast<const float4*>(g_row)[b * ROW_VEC4 + t];

    size_t base = ((size_t)b * SEQ + s0) * ROW_VEC4 + t;
    #pragma unroll
    for (int s = 0; s < S_PER_BLOCK; ++s) {
        out[base + (size_t)s * ROW_VEC4] = v;
    }
}

// ---------------------------------------------------------------------------
// Inputs (metadata order): 0 query, 1 key, 2 value, 3 Wq, 4 bq,
//                          5 Wk, 6 bk, 7 Wv, 8 bv, 9 Wo, 10 bo
// softmax over kv_len=1 is identically 1 -> query/key/Wq/bq/Wk/bk are dead.
// ---------------------------------------------------------------------------
extern "C" void kernel_launch(void* const* d_in, const int* in_sizes, int n_in,
                              void* d_out, int out_size) {
    const float* value = (const float*)d_in[2];
    const float* Wv    = (const float*)d_in[7];
    const float* bv    = (const float*)d_in[8];
    const float* Wo    = (const float*)d_in[9];
    const float* bo    = (const float*)d_in[10];
    float* out = (float*)d_out;

    prologue_kernel<<<BATCH, 1024>>>(value, Wv, bv, bo);

    dim3 gridB(D_MODEL / 256, NUM_HEADS);
    row_partial_kernel<<<gridB, 256>>>(Wo);

    dim3 gridC(SEQ / S_PER_BLOCK, BATCH);
    broadcast_kernel<<<gridC, 256>>>((float4*)out);
}

// round 10
// speedup vs baseline: 3.0752x; 1.1060x over previous
#include <cuda_runtime.h>

// Shapes (fixed by the problem)
#define D_MODEL   1024
#define HEAD_DIM  64
#define NUM_HEADS 16
#define BATCH     8
#define SEQ       4096
#define KSLICES   8          // K-split for the V GEMV

// Scratch (allocation-free rule: __device__ globals).
// Both buffers are fully (over)written every replay — no cross-replay state.
__device__ float g_Vpart[KSLICES * BATCH * HEAD_DIM];  // partial V sums
__device__ float g_row[BATCH * D_MODEL];               // row[b] accumulator

// ---------------------------------------------------------------------------
// Kernel A: V partials + g_row reset.
//   g_Vpart[ks][b][d] = sum_{i in slice ks} value[b,i] * Wv[i,d]
//   g_row[b,j] = bo[j]   (reset; kernel B atomically accumulates onto it)
// grid = (KSLICES=8, BATCH=8) = 64 CTAs, 256 threads (64 d-lanes x 4 sub-slices).
// Wv (256 KB) is read exactly once, spread across 64 SMs -> latency hidden.
// ---------------------------------------------------------------------------
__global__ __launch_bounds__(256, 1)
void v_partial_kernel(const float* __restrict__ value,
                      const float* __restrict__ Wv,
                      const float* __restrict__ bo) {
    const int ks = blockIdx.x;           // 0..7 K-slice
    const int b  = blockIdx.y;           // 0..7 batch
    const int t  = threadIdx.x;          // 0..255

    // distributed g_row reset: 64 blocks x 256 threads = 16384 >= 8192
    const int gid = (b * KSLICES + ks) * 256 + t;
    if (gid < BATCH * D_MODEL)
        g_row[gid] = bo[gid & (D_MODEL - 1)];

    const int d   = t & (HEAD_DIM - 1);  // 0..63
    const int sub = t >> 6;              // 0..3
    const int i0  = ks * (D_MODEL / KSLICES) + sub * (D_MODEL / KSLICES / 4);
    const float* vrow = value + b * D_MODEL;

    float acc = 0.f;
    #pragma unroll 8
    for (int i = 0; i < D_MODEL / KSLICES / 4; ++i) {   // 32 iters
        const int ii = i0 + i;
        acc += vrow[ii] * Wv[ii * HEAD_DIM + d];
    }

    __shared__ float red[4][HEAD_DIM];
    red[sub][d] = acc;
    __syncthreads();
    if (sub == 0) {
        g_Vpart[(ks * BATCH + b) * HEAD_DIM + d] =
            red[0][d] + red[1][d] + red[2][d] + red[3][d];
    }
}

// ---------------------------------------------------------------------------
// Kernel B: g_row[b,j] += sum_{ii<64} V[b,ii] * Wo[(h*64+ii)*1024 + j]
// where V[b,ii] = bv[ii] + sum_ks g_Vpart[ks][b][ii]  (folded into smem load).
// grid = (4 j-chunks, 16 h) = 64 CTAs, 256 threads. Wo (4 MB) read once,
// fully coalesced; all 8 batches accumulated per thread.
// ---------------------------------------------------------------------------
__global__ __launch_bounds__(256, 1)
void row_partial_kernel(const float* __restrict__ Wo,
                        const float* __restrict__ bv) {
    const int t = threadIdx.x;                 // 0..255
    const int j = blockIdx.x * 256 + t;        // 0..1023
    const int h = blockIdx.y;                  // 0..15

    __shared__ float sV[BATCH * HEAD_DIM];     // 512 floats
    #pragma unroll
    for (int e = t; e < BATCH * HEAD_DIM; e += 256) {
        const int d = e & (HEAD_DIM - 1);
        float s = bv[d];
        #pragma unroll
        for (int ks = 0; ks < KSLICES; ++ks)
            s += g_Vpart[ks * BATCH * HEAD_DIM + e];
        sV[e] = s;
    }
    __syncthreads();

    float acc[BATCH];
    #pragma unroll
    for (int b = 0; b < BATCH; ++b) acc[b] = 0.f;

    const float* wcol = Wo + (size_t)(h * HEAD_DIM) * D_MODEL + j;
    #pragma unroll 8
    for (int ii = 0; ii < HEAD_DIM; ++ii) {
        const float w = wcol[ii * D_MODEL];    // coalesced across threads
        #pragma unroll
        for (int b = 0; b < BATCH; ++b)
            acc[b] += sV[b * HEAD_DIM + ii] * w;   // smem broadcast
    }

    #pragma unroll
    for (int b = 0; b < BATCH; ++b)
        atomicAdd(&g_row[b * D_MODEL + j], acc[b]);
}

// ---------------------------------------------------------------------------
// Kernel C: out[b,s,:] = row[b,:]  (134 MB of streaming float4 stores)
// grid = (SEQ/32, 8), 256 threads; each thread stamps its float4 32 times.
// ---------------------------------------------------------------------------
#define S_PER_BLOCK 32
#define ROW_VEC4    (D_MODEL / 4)   // 256

__global__ __launch_bounds__(256, 8)
void broadcast_kernel(float4* __restrict__ out) {
    const int b  = blockIdx.y;
    const int s0 = blockIdx.x * S_PER_BLOCK;
    const int t  = threadIdx.x;

    const float4 v = reinterpret_cast<const float4*>(g_row)[b * ROW_VEC4 + t];

    size_t base = ((size_t)b * SEQ + s0) * ROW_VEC4 + t;
    #pragma unroll
    for (int s = 0; s < S_PER_BLOCK; ++s) {
        out[base + (size_t)s * ROW_VEC4] = v;
    }
}

// ---------------------------------------------------------------------------
// Inputs (metadata order): 0 query, 1 key, 2 value, 3 Wq, 4 bq,
//                          5 Wk, 6 bk, 7 Wv, 8 bv, 9 Wo, 10 bo
// softmax over kv_len=1 is identically 1 -> query/key/Wq/bq/Wk/bk are dead.
// ---------------------------------------------------------------------------
extern "C" void kernel_launch(void* const* d_in, const int* in_sizes, int n_in,
                              void* d_out, int out_size) {
    const float* value = (const float*)d_in[2];
    const float* Wv    = (const float*)d_in[7];
    const float* bv    = (const float*)d_in[8];
    const float* Wo    = (const float*)d_in[9];
    const float* bo    = (const float*)d_in[10];
    float* out = (float*)d_out;

    dim3 gridA(KSLICES, BATCH);
    v_partial_kernel<<<gridA, 256>>>(value, Wv, bo);

    dim3 gridB(D_MODEL / 256, NUM_HEADS);
    row_partial_kernel<<<gridB, 256>>>(Wo, bv);

    dim3 gridC(SEQ / S_PER_BLOCK, BATCH);
    broadcast_kernel<<<gridC, 256>>>((float4*)out);
}